// round 12
// baseline (speedup 1.0000x reference)
#include <cuda_runtime.h>
#include <cuda_bf16.h>
#include <math.h>

#define NN 50000
#define DD 128
#define EE 800000
#define LL 3

// ---------------- scratch (device globals: no allocation allowed) ----------------
// g_zin reused as split-bf16 A1 image: h = first NN*128 bf16, l = next NN*128
__device__ float g_zin[NN * DD];
// g_z1 reused as split-bf16 A2 image: h = first NN*256 bf16, l = next NN*256
__device__ float g_z1[NN * 2 * DD];
__device__ float g_hA[NN * DD];
__device__ float g_hB[NN * DD];
__device__ int   g_cnt[NN];
__device__ int   g_off[NN + 1];
__device__ int   g_cursor[NN];
__device__ int   g_esrc[EE];
__device__ int   g_boff[256];
__device__ float g_sc1[LL * 256];
__device__ float g_sh1[LL * 256];
__device__ float g_sc2[2 * 128];
__device__ float g_sh2[2 * 128];
// split-bf16 weight images in the GEMM's per-thread B-load order:
__device__ uint4 g_w1img[6 * 4096];
__device__ uint4 g_w2img[3 * 8192];

// ---------------- helpers ----------------
__device__ __forceinline__ void split8(const float* f, uint4* h, uint4* l) {
    union { uint4 u; __nv_bfloat162 p[4]; } H, Lo;
#pragma unroll
    for (int j = 0; j < 4; j++) {
        float x0 = f[2 * j], x1 = f[2 * j + 1];
        __nv_bfloat16 h0 = __float2bfloat16(x0), h1 = __float2bfloat16(x1);
        H.p[j] = __nv_bfloat162(h0, h1);
        Lo.p[j] = __nv_bfloat162(__float2bfloat16(x0 - __bfloat162float(h0)),
                                 __float2bfloat16(x1 - __bfloat162float(h1)));
    }
    *h = H.u; *l = Lo.u;
}

// ---------------- folded BN params ----------------
__global__ void k_prep(const float* __restrict__ b1, const float* __restrict__ g1,
                       const float* __restrict__ be1, const float* __restrict__ m1,
                       const float* __restrict__ v1, const float* __restrict__ b2,
                       const float* __restrict__ go, const float* __restrict__ bo,
                       const float* __restrict__ mo, const float* __restrict__ vo) {
    int i = blockIdx.x * blockDim.x + threadIdx.x;
    if (i < LL * 256) {
        float sc = g1[i] * rsqrtf(v1[i] + 1e-5f);
        g_sc1[i] = sc;
        g_sh1[i] = be1[i] - m1[i] * sc + b1[i] * sc;
    }
    if (i < 2 * 128) {
        float sc = go[i] * rsqrtf(vo[i] + 1e-5f);
        g_sc2[i] = sc;
        g_sh2[i] = bo[i] - mo[i] * sc + b2[i] * sc;
    }
}

// ---------------- weight images ----------------
__global__ void k_wimg(const float* __restrict__ W1, const float* __restrict__ W2) {
    int t = blockIdx.x * 256 + threadIdx.x;  // 49152 total
    int half = t / 24576;
    int r = t % 24576;
    float f[8];
    uint4 h, l4;
    if (half == 0) {
        int lny = r >> 12;
        int rem = r & 4095;
        int kt = rem >> 9;
        int hl = (rem >> 8) & 1;
        int c = rem & 255;
        int krow = c >> 4, chunk = c & 15;
        int l = lny >> 1, ny = lny & 1;
        int k = kt * 16 + krow;
        int n = ny * 128 + chunk * 8;
#pragma unroll
        for (int j = 0; j < 8; j++)
            f[j] = W1[(size_t)l * 128 * 256 + (size_t)k * 256 + n + j];
        split8(f, &h, &l4);
        g_w1img[r] = hl ? l4 : h;
    } else {
        int l = r >> 13;
        int rem = r & 8191;
        int kt = rem >> 9;
        int hl = (rem >> 8) & 1;
        int c = rem & 255;
        int krow = c >> 4, chunk = c & 15;
        int k = kt * 16 + krow;
        int n = chunk * 8;
#pragma unroll
        for (int j = 0; j < 8; j++)
            f[j] = W2[(size_t)l * 256 * 128 + (size_t)k * 128 + n + j];
        split8(f, &h, &l4);
        g_w2img[r] = hl ? l4 : h;
    }
}

// ---------------- CSR build ----------------
__global__ void k_zero_cnt() {
    int i = blockIdx.x * blockDim.x + threadIdx.x;
    if (i < NN) g_cnt[i] = 0;
}
__global__ void k_hist(const int* __restrict__ dstp) {
    int e = blockIdx.x * blockDim.x + threadIdx.x;
    if (e < EE) atomicAdd(&g_cnt[dstp[e]], 1);
}
__global__ void k_bsum() {
    __shared__ int sh[8];
    int i = blockIdx.x * 256 + threadIdx.x;
    int lane = threadIdx.x & 31, warp = threadIdx.x >> 5;
    int v = (i < NN) ? g_cnt[i] : 0;
#pragma unroll
    for (int o = 16; o; o >>= 1) v += __shfl_xor_sync(0xffffffffu, v, o);
    if (lane == 0) sh[warp] = v;
    __syncthreads();
    if (threadIdx.x == 0) {
        int s = 0;
#pragma unroll
        for (int w = 0; w < 8; w++) s += sh[w];
        g_boff[blockIdx.x] = s;
    }
}
__global__ void k_bscan() {
    __shared__ int s[256];
    int t = threadIdx.x;
    s[t] = (t < 196) ? g_boff[t] : 0;
    __syncthreads();
    for (int off = 1; off < 256; off <<= 1) {
        int v = (t >= off) ? s[t - off] : 0;
        __syncthreads();
        s[t] += v;
        __syncthreads();
    }
    g_boff[t] = (t > 0) ? s[t - 1] : 0;
}
__global__ void k_apply() {
    __shared__ int s[256];
    int b = blockIdx.x, t = threadIdx.x;
    int i = b * 256 + t;
    int c = (i < NN) ? g_cnt[i] : 0;
    s[t] = c;
    __syncthreads();
    for (int off = 1; off < 256; off <<= 1) {
        int v = (t >= off) ? s[t - off] : 0;
        __syncthreads();
        s[t] += v;
        __syncthreads();
    }
    if (i < NN) {
        int o = g_boff[b] + s[t] - c;
        g_off[i] = o;
        g_cursor[i] = o;
    }
    if (b == 0 && t == 0) g_off[NN] = EE;
}
__global__ void k_fill(const int* __restrict__ srcp, const int* __restrict__ dstp) {
    int e = blockIdx.x * blockDim.x + threadIdx.x;
    if (e < EE) {
        int d = dstp[e];
        int pos = atomicAdd(&g_cursor[d], 1);
        g_esrc[pos] = srcp[e];
    }
}

// ---------------- aggregation -> split-bf16 A1 image ----------------
__global__ void k_agg(const float* __restrict__ hin, const float* __restrict__ epsp, int l,
                      __nv_bfloat16* __restrict__ Ahp, __nv_bfloat16* __restrict__ Alp) {
    int warp = (blockIdx.x * blockDim.x + threadIdx.x) >> 5;
    int lane = threadIdx.x & 31;
    if (warp >= NN) return;
    int beg = g_off[warp];
    int end = g_off[warp + 1];
    float4 acc = make_float4(0.f, 0.f, 0.f, 0.f);
    for (int j = beg; j < end; j += 32) {
        int myidx = j + lane;
        int s = (myidx < end) ? g_esrc[myidx] : 0;
        int cnt = min(32, end - j);
        int t = 0;
        for (; t + 4 <= cnt; t += 4) {
            int s0 = __shfl_sync(0xffffffffu, s, t);
            int s1 = __shfl_sync(0xffffffffu, s, t + 1);
            int s2 = __shfl_sync(0xffffffffu, s, t + 2);
            int s3 = __shfl_sync(0xffffffffu, s, t + 3);
            float4 v0 = *(const float4*)(hin + (size_t)s0 * DD + lane * 4);
            float4 v1 = *(const float4*)(hin + (size_t)s1 * DD + lane * 4);
            float4 v2 = *(const float4*)(hin + (size_t)s2 * DD + lane * 4);
            float4 v3 = *(const float4*)(hin + (size_t)s3 * DD + lane * 4);
            acc.x += v0.x + v1.x + v2.x + v3.x;
            acc.y += v0.y + v1.y + v2.y + v3.y;
            acc.z += v0.z + v1.z + v2.z + v3.z;
            acc.w += v0.w + v1.w + v2.w + v3.w;
        }
        for (; t < cnt; t++) {
            int sj = __shfl_sync(0xffffffffu, s, t);
            float4 v = *(const float4*)(hin + (size_t)sj * DD + lane * 4);
            acc.x += v.x; acc.y += v.y; acc.z += v.z; acc.w += v.w;
        }
    }
    float ev = 1.0f + epsp[l];
    float4 hv = *(const float4*)(hin + (size_t)warp * DD + lane * 4);
    acc.x += ev * hv.x; acc.y += ev * hv.y; acc.z += ev * hv.z; acc.w += ev * hv.w;
    // split-bf16 write
    union { uint2 u; __nv_bfloat162 p[2]; } H, Lo;
    const float f[4] = {acc.x, acc.y, acc.z, acc.w};
#pragma unroll
    for (int j = 0; j < 2; j++) {
        __nv_bfloat16 h0 = __float2bfloat16(f[2 * j]);
        __nv_bfloat16 h1 = __float2bfloat16(f[2 * j + 1]);
        H.p[j] = __nv_bfloat162(h0, h1);
        Lo.p[j] = __nv_bfloat162(__float2bfloat16(f[2 * j] - __bfloat162float(h0)),
                                 __float2bfloat16(f[2 * j + 1] - __bfloat162float(h1)));
    }
    *(uint2*)(Ahp + (size_t)warp * DD + lane * 4) = H.u;
    *(uint2*)(Alp + (size_t)warp * DD + lane * 4) = Lo.u;
}

// ---------------- split-bf16 tensor-core GEMM, all-cp.async mainloop ----------------
#define BM 128
#define BN 128
#define BK 16
#define ASTR 24
#define BSTR 136

__device__ __forceinline__ void ldsm4(unsigned r[4], const __nv_bfloat16* p) {
    unsigned addr = (unsigned)__cvta_generic_to_shared(p);
    asm volatile("ldmatrix.sync.aligned.m8n8.x4.shared.b16 {%0,%1,%2,%3}, [%4];"
                 : "=r"(r[0]), "=r"(r[1]), "=r"(r[2]), "=r"(r[3]) : "r"(addr));
}
__device__ __forceinline__ void ldsm4t(unsigned r[4], const __nv_bfloat16* p) {
    unsigned addr = (unsigned)__cvta_generic_to_shared(p);
    asm volatile("ldmatrix.sync.aligned.m8n8.x4.trans.shared.b16 {%0,%1,%2,%3}, [%4];"
                 : "=r"(r[0]), "=r"(r[1]), "=r"(r[2]), "=r"(r[3]) : "r"(addr));
}
__device__ __forceinline__ void mma16816(float c[4], const unsigned a[4], unsigned b0, unsigned b1) {
    asm volatile("mma.sync.aligned.m16n8k16.row.col.f32.bf16.bf16.f32 "
                 "{%0,%1,%2,%3},{%4,%5,%6,%7},{%8,%9},{%0,%1,%2,%3};"
                 : "+f"(c[0]), "+f"(c[1]), "+f"(c[2]), "+f"(c[3])
                 : "r"(a[0]), "r"(a[1]), "r"(a[2]), "r"(a[3]), "r"(b0), "r"(b1));
}
__device__ __forceinline__ void cpasync16(void* sdst, const void* gsrc) {
    unsigned a = (unsigned)__cvta_generic_to_shared(sdst);
    asm volatile("cp.async.cg.shared.global [%0], [%1], 16;" :: "r"(a), "l"(gsrc));
}
__device__ __forceinline__ void cpasync16z(void* sdst, const void* gsrc, int srcsz) {
    unsigned a = (unsigned)__cvta_generic_to_shared(sdst);
    asm volatile("cp.async.cg.shared.global [%0], [%1], 16, %2;"
                 :: "r"(a), "l"(gsrc), "r"(srcsz));
}
#define CP_COMMIT() asm volatile("cp.async.commit_group;" ::: "memory")
#define CP_WAIT0()  asm volatile("cp.async.wait_group 0;" ::: "memory")

// outmode: 0 = fp32 out, acc+shift ; 1 = fp32 out, relu(acc*sc+sh) ;
//          2 = split-bf16 image out, relu(acc*sc+sh)
__global__ __launch_bounds__(256, 2) void k_gemm(
    const __nv_bfloat16* __restrict__ Ahg, const __nv_bfloat16* __restrict__ Alg,
    const uint4* __restrict__ Bimg,
    float* __restrict__ Cf, __nv_bfloat16* __restrict__ Ch, __nv_bfloat16* __restrict__ Cl,
    int M, int Nn, int K,
    const float* __restrict__ scale, const float* __restrict__ shift, int outmode) {
    __shared__ __align__(16) __nv_bfloat16 Ahs[2][BM * ASTR];
    __shared__ __align__(16) __nv_bfloat16 Als[2][BM * ASTR];
    __shared__ __align__(16) __nv_bfloat16 Bhs[2][BK * BSTR];
    __shared__ __align__(16) __nv_bfloat16 Bls[2][BK * BSTR];

    int tid = threadIdx.x;
    int lane = tid & 31, warp = tid >> 5;
    int wm = (warp >> 1) * 32;
    int wn = (warp & 1) * 64;
    int m0 = blockIdx.x * BM, n0 = blockIdx.y * BN;
    Bimg += (size_t)blockIdx.y * 4096;

    float acc[2][8][4];
#pragma unroll
    for (int i = 0; i < 2; i++)
#pragma unroll
        for (int j = 0; j < 8; j++)
#pragma unroll
            for (int q = 0; q < 4; q++) acc[i][j][q] = 0.f;

    // A cp.async: thread -> (row = tid>>1, khalf = tid&1)
    const int a_row = tid >> 1;
    const int a_kh = tid & 1;
    const int grow = m0 + a_row;
    const int asz = (grow < M) ? 16 : 0;
    const __nv_bfloat16* aph = Ahg + (size_t)grow * K + a_kh * 8;
    const __nv_bfloat16* apl = Alg + (size_t)grow * K + a_kh * 8;
    const unsigned a_sm = a_row * ASTR + a_kh * 8;
    // B cp.async: thread -> (krow = tid>>4, chunk = tid&15)
    const int b_krow = tid >> 4, b_chunk = tid & 15;
    const unsigned b_sm = b_krow * BSTR + b_chunk * 8;

#define CPTILE(kt, st)                                                                   \
    {                                                                                    \
        cpasync16z(&Ahs[st][a_sm], aph + (kt) * BK, asz);                                \
        cpasync16z(&Als[st][a_sm], apl + (kt) * BK, asz);                                \
        cpasync16(&Bhs[st][b_sm], Bimg + (kt) * 512 + tid);                              \
        cpasync16(&Bls[st][b_sm], Bimg + (kt) * 512 + 256 + tid);                        \
        CP_COMMIT();                                                                     \
    }

    const int a_lrow = wm + (lane & 15);
    const int a_lkof = (lane >> 4) * 8;
    const int b_lk = (lane & 7) + ((lane >> 3) & 1) * 8;
    const int b_lnof = ((lane >> 4) & 1) * 8;

#define PASS(AS, BS)                                                                     \
    {                                                                                    \
        unsigned afr[2][4], bfr[4][4];                                                   \
        _Pragma("unroll") for (int mt = 0; mt < 2; mt++)                                 \
            ldsm4(afr[mt], &AS[(a_lrow + mt * 16) * ASTR + a_lkof]);                     \
        _Pragma("unroll") for (int ntp = 0; ntp < 4; ntp++)                              \
            ldsm4t(bfr[ntp], &BS[b_lk * BSTR + wn + ntp * 16 + b_lnof]);                 \
        _Pragma("unroll") for (int mt = 0; mt < 2; mt++)                                 \
            _Pragma("unroll") for (int ntp = 0; ntp < 4; ntp++) {                        \
                mma16816(acc[mt][2 * ntp], afr[mt], bfr[ntp][0], bfr[ntp][1]);           \
                mma16816(acc[mt][2 * ntp + 1], afr[mt], bfr[ntp][2], bfr[ntp][3]);       \
            }                                                                            \
    }

    CPTILE(0, 0);
    CP_WAIT0();
    __syncthreads();

    int nIter = K / BK;
    for (int t = 0; t < nIter; t++) {
        int cur = t & 1, nxt = cur ^ 1;
        bool have = (t + 1 < nIter);
        if (have) CPTILE(t + 1, nxt);
        PASS(Ahs[cur], Bhs[cur]);
        PASS(Ahs[cur], Bls[cur]);
        PASS(Als[cur], Bhs[cur]);
        CP_WAIT0();
        __syncthreads();
    }

    int grp = lane >> 2, tig = lane & 3;
#pragma unroll
    for (int mt = 0; mt < 2; mt++) {
#pragma unroll
        for (int nt = 0; nt < 8; nt++) {
            int col = n0 + wn + nt * 8 + tig * 2;
            float2 sc = make_float2(0.f, 0.f), sh;
            sh = *(const float2*)(shift + col);
            if (outmode >= 1) sc = *(const float2*)(scale + col);
            int row0 = m0 + wm + mt * 16 + grp;
            int row1 = row0 + 8;
            float* c = acc[mt][nt];
            float2 o0, o1;
            if (outmode >= 1) {
                o0.x = fmaxf(c[0] * sc.x + sh.x, 0.f);
                o0.y = fmaxf(c[1] * sc.y + sh.y, 0.f);
                o1.x = fmaxf(c[2] * sc.x + sh.x, 0.f);
                o1.y = fmaxf(c[3] * sc.y + sh.y, 0.f);
            } else {
                o0.x = c[0] + sh.x;
                o0.y = c[1] + sh.y;
                o1.x = c[2] + sh.x;
                o1.y = c[3] + sh.y;
            }
            if (outmode == 2) {
                union { unsigned u; __nv_bfloat162 p; } h0, h1, l0, l1;
                __nv_bfloat16 a0 = __float2bfloat16(o0.x), a1 = __float2bfloat16(o0.y);
                __nv_bfloat16 b0 = __float2bfloat16(o1.x), b1 = __float2bfloat16(o1.y);
                h0.p = __nv_bfloat162(a0, a1);
                h1.p = __nv_bfloat162(b0, b1);
                l0.p = __nv_bfloat162(__float2bfloat16(o0.x - __bfloat162float(a0)),
                                      __float2bfloat16(o0.y - __bfloat162float(a1)));
                l1.p = __nv_bfloat162(__float2bfloat16(o1.x - __bfloat162float(b0)),
                                      __float2bfloat16(o1.y - __bfloat162float(b1)));
                if (row0 < M) {
                    *(unsigned*)(Ch + (size_t)row0 * Nn + col) = h0.u;
                    *(unsigned*)(Cl + (size_t)row0 * Nn + col) = l0.u;
                }
                if (row1 < M) {
                    *(unsigned*)(Ch + (size_t)row1 * Nn + col) = h1.u;
                    *(unsigned*)(Cl + (size_t)row1 * Nn + col) = l1.u;
                }
            } else {
                if (row0 < M) *(float2*)(Cf + (size_t)row0 * Nn + col) = o0;
                if (row1 < M) *(float2*)(Cf + (size_t)row1 * Nn + col) = o1;
            }
        }
    }
#undef CPTILE
#undef PASS
}

// ---------------- log_softmax over D=128, warp per row, in place ----------------
__global__ void k_lsm(float* __restrict__ out) {
    int warp = (blockIdx.x * blockDim.x + threadIdx.x) >> 5;
    int lane = threadIdx.x & 31;
    if (warp >= NN) return;
    float4 v = *(float4*)(out + (size_t)warp * DD + lane * 4);
    float mx = fmaxf(fmaxf(v.x, v.y), fmaxf(v.z, v.w));
#pragma unroll
    for (int o = 16; o; o >>= 1) mx = fmaxf(mx, __shfl_xor_sync(0xffffffffu, mx, o));
    float s = expf(v.x - mx) + expf(v.y - mx) + expf(v.z - mx) + expf(v.w - mx);
#pragma unroll
    for (int o = 16; o; o >>= 1) s += __shfl_xor_sync(0xffffffffu, s, o);
    float lse = mx + logf(s);
    v.x -= lse; v.y -= lse; v.z -= lse; v.w -= lse;
    *(float4*)(out + (size_t)warp * DD + lane * 4) = v;
}

// ---------------- launch ----------------
extern "C" void kernel_launch(void* const* d_in, const int* in_sizes, int n_in,
                              void* d_out, int out_size) {
    const float* x   = (const float*)d_in[0];
    const int*   ei  = (const int*)d_in[1];
    const float* W1  = (const float*)d_in[2];
    const float* b1  = (const float*)d_in[3];
    const float* g1  = (const float*)d_in[4];
    const float* be1 = (const float*)d_in[5];
    const float* m1  = (const float*)d_in[6];
    const float* v1  = (const float*)d_in[7];
    const float* W2  = (const float*)d_in[8];
    const float* b2  = (const float*)d_in[9];
    const float* eps = (const float*)d_in[10];
    const float* go  = (const float*)d_in[11];
    const float* bo  = (const float*)d_in[12];
    const float* mo  = (const float*)d_in[13];
    const float* vo  = (const float*)d_in[14];
    const int* srcp = ei;
    const int* dstp = ei + EE;

    float *zin, *z1p, *hA, *hB, *sc1, *sh1, *sc2, *sh2;
    uint4 *w1i, *w2i;
    cudaGetSymbolAddress((void**)&zin, g_zin);
    cudaGetSymbolAddress((void**)&z1p, g_z1);
    cudaGetSymbolAddress((void**)&hA, g_hA);
    cudaGetSymbolAddress((void**)&hB, g_hB);
    cudaGetSymbolAddress((void**)&sc1, g_sc1);
    cudaGetSymbolAddress((void**)&sh1, g_sh1);
    cudaGetSymbolAddress((void**)&sc2, g_sc2);
    cudaGetSymbolAddress((void**)&sh2, g_sh2);
    cudaGetSymbolAddress((void**)&w1i, g_w1img);
    cudaGetSymbolAddress((void**)&w2i, g_w2img);

    __nv_bfloat16* A1h = (__nv_bfloat16*)zin;
    __nv_bfloat16* A1l = A1h + (size_t)NN * DD;
    __nv_bfloat16* A2h = (__nv_bfloat16*)z1p;
    __nv_bfloat16* A2l = A2h + (size_t)NN * 2 * DD;

    k_prep<<<3, 256>>>(b1, g1, be1, m1, v1, b2, go, bo, mo, vo);
    k_wimg<<<192, 256>>>(W1, W2);
    k_zero_cnt<<<(NN + 255) / 256, 256>>>();
    k_hist<<<(EE + 255) / 256, 256>>>(dstp);
    const int SB = (NN + 255) / 256;  // 196
    k_bsum<<<SB, 256>>>();
    k_bscan<<<1, 256>>>();
    k_apply<<<SB, 256>>>();
    k_fill<<<(EE + 255) / 256, 256>>>(srcp, dstp);

    const int MT = (NN + BM - 1) / BM;  // 391
    for (int l = 0; l < LL; l++) {
        const float* hin = (l == 0) ? x : ((l == 1) ? hA : hB);
        k_agg<<<(NN * 32 + 255) / 256, 256>>>(hin, eps, l, A1h, A1l);
        // GEMM1: A1 image [NN,128] -> z1 split-bf16 image [NN,256]
        k_gemm<<<dim3(MT, 2), 256>>>(A1h, A1l, w1i + (size_t)l * 2 * 4096,
                                     nullptr, A2h, A2l,
                                     NN, 2 * DD, DD, sc1 + l * 256, sh1 + l * 256, 2);
        if (l < 2) {
            float* hout = (l == 0) ? hA : hB;
            k_gemm<<<dim3(MT, 1), 256>>>(A2h, A2l, w2i + (size_t)l * 8192,
                                         hout, nullptr, nullptr,
                                         NN, DD, 2 * DD, sc2 + l * 128, sh2 + l * 128, 1);
        } else {
            k_gemm<<<dim3(MT, 1), 256>>>(A2h, A2l, w2i + (size_t)2 * 8192,
                                         (float*)d_out, nullptr, nullptr,
                                         NN, DD, 2 * DD, nullptr, b2 + 2 * 128, 0);
        }
    }
    k_lsm<<<(NN * 32 + 255) / 256, 256>>>((float*)d_out);
}

// round 13
// speedup vs baseline: 1.1548x; 1.1548x over previous
#include <cuda_runtime.h>
#include <cuda_bf16.h>
#include <math.h>

#define NN 50000
#define DD 128
#define EE 800000
#define LL 3

// ---------------- scratch (device globals: no allocation allowed) ----------------
__device__ float g_zin[NN * DD];
__device__ float g_z1[NN * 2 * DD];
__device__ float g_hA[NN * DD];
__device__ float g_hB[NN * DD];
__device__ int   g_cnt[NN];
__device__ int   g_off[NN + 1];
__device__ int   g_cursor[NN];
__device__ int   g_esrc[EE];
__device__ int   g_boff[256];
__device__ float g_sc1[LL * 256];
__device__ float g_sh1[LL * 256];
__device__ float g_sc2[2 * 128];
__device__ float g_sh2[2 * 128];
// split-bf16 weight images in the GEMM's per-thread B-load order:
// W1: per (l,ny) tile: [kt(8)][hl(2)][256 uint4]   -> 6 * 4096 uint4
// W2: per l:           [kt(16)][hl(2)][256 uint4]  -> 3 * 8192 uint4
__device__ uint4 g_w1img[6 * 4096];
__device__ uint4 g_w2img[3 * 8192];

// ---------------- helpers ----------------
__device__ __forceinline__ void split8(const float* f, uint4* h, uint4* l) {
    union { uint4 u; __nv_bfloat162 p[4]; } H, Lo;
#pragma unroll
    for (int j = 0; j < 4; j++) {
        float x0 = f[2 * j], x1 = f[2 * j + 1];
        __nv_bfloat16 h0 = __float2bfloat16(x0), h1 = __float2bfloat16(x1);
        H.p[j] = __nv_bfloat162(h0, h1);
        Lo.p[j] = __nv_bfloat162(__float2bfloat16(x0 - __bfloat162float(h0)),
                                 __float2bfloat16(x1 - __bfloat162float(h1)));
    }
    *h = H.u; *l = Lo.u;
}

// ---------------- folded BN params ----------------
__global__ void k_prep(const float* __restrict__ b1, const float* __restrict__ g1,
                       const float* __restrict__ be1, const float* __restrict__ m1,
                       const float* __restrict__ v1, const float* __restrict__ b2,
                       const float* __restrict__ go, const float* __restrict__ bo,
                       const float* __restrict__ mo, const float* __restrict__ vo) {
    int i = blockIdx.x * blockDim.x + threadIdx.x;
    if (i < LL * 256) {
        float sc = g1[i] * rsqrtf(v1[i] + 1e-5f);
        g_sc1[i] = sc;
        g_sh1[i] = be1[i] - m1[i] * sc + b1[i] * sc;
    }
    if (i < 2 * 128) {
        float sc = go[i] * rsqrtf(vo[i] + 1e-5f);
        g_sc2[i] = sc;
        g_sh2[i] = bo[i] - mo[i] * sc + b2[i] * sc;
    }
}

// ---------------- weight images ----------------
__global__ void k_wimg(const float* __restrict__ W1, const float* __restrict__ W2) {
    int t = blockIdx.x * 256 + threadIdx.x;  // 49152 total
    int half = t / 24576;
    int r = t % 24576;
    float f[8];
    uint4 h, l4;
    if (half == 0) {
        int lny = r >> 12;
        int rem = r & 4095;
        int kt = rem >> 9;
        int hl = (rem >> 8) & 1;
        int c = rem & 255;
        int krow = c >> 4, chunk = c & 15;
        int l = lny >> 1, ny = lny & 1;
        int k = kt * 16 + krow;
        int n = ny * 128 + chunk * 8;
#pragma unroll
        for (int j = 0; j < 8; j++)
            f[j] = W1[(size_t)l * 128 * 256 + (size_t)k * 256 + n + j];
        split8(f, &h, &l4);
        g_w1img[r] = hl ? l4 : h;
    } else {
        int l = r >> 13;
        int rem = r & 8191;
        int kt = rem >> 9;
        int hl = (rem >> 8) & 1;
        int c = rem & 255;
        int krow = c >> 4, chunk = c & 15;
        int k = kt * 16 + krow;
        int n = chunk * 8;
#pragma unroll
        for (int j = 0; j < 8; j++)
            f[j] = W2[(size_t)l * 256 * 128 + (size_t)k * 128 + n + j];
        split8(f, &h, &l4);
        g_w2img[r] = hl ? l4 : h;
    }
}

// ---------------- CSR build ----------------
__global__ void k_zero_cnt() {
    int i = blockIdx.x * blockDim.x + threadIdx.x;
    if (i < NN) g_cnt[i] = 0;
}
// 2 edges per thread
__global__ void k_hist(const int* __restrict__ dstp) {
    int e2 = blockIdx.x * blockDim.x + threadIdx.x;
    if (e2 * 2 < EE) {
        int2 d = *(const int2*)(dstp + e2 * 2);
        atomicAdd(&g_cnt[d.x], 1);
        atomicAdd(&g_cnt[d.y], 1);
    }
}
__global__ void k_bsum() {
    __shared__ int sh[8];
    int i = blockIdx.x * 256 + threadIdx.x;
    int lane = threadIdx.x & 31, warp = threadIdx.x >> 5;
    int v = (i < NN) ? g_cnt[i] : 0;
#pragma unroll
    for (int o = 16; o; o >>= 1) v += __shfl_xor_sync(0xffffffffu, v, o);
    if (lane == 0) sh[warp] = v;
    __syncthreads();
    if (threadIdx.x == 0) {
        int s = 0;
#pragma unroll
        for (int w = 0; w < 8; w++) s += sh[w];
        g_boff[blockIdx.x] = s;
    }
}
__global__ void k_bscan() {
    __shared__ int s[256];
    int t = threadIdx.x;
    s[t] = (t < 196) ? g_boff[t] : 0;
    __syncthreads();
    for (int off = 1; off < 256; off <<= 1) {
        int v = (t >= off) ? s[t - off] : 0;
        __syncthreads();
        s[t] += v;
        __syncthreads();
    }
    g_boff[t] = (t > 0) ? s[t - 1] : 0;
}
__global__ void k_apply() {
    __shared__ int s[256];
    int b = blockIdx.x, t = threadIdx.x;
    int i = b * 256 + t;
    int c = (i < NN) ? g_cnt[i] : 0;
    s[t] = c;
    __syncthreads();
    for (int off = 1; off < 256; off <<= 1) {
        int v = (t >= off) ? s[t - off] : 0;
        __syncthreads();
        s[t] += v;
        __syncthreads();
    }
    if (i < NN) {
        int o = g_boff[b] + s[t] - c;
        g_off[i] = o;
        g_cursor[i] = o;
    }
    if (b == 0 && t == 0) g_off[NN] = EE;
}
// 2 edges per thread
__global__ void k_fill(const int* __restrict__ srcp, const int* __restrict__ dstp) {
    int e2 = blockIdx.x * blockDim.x + threadIdx.x;
    if (e2 * 2 < EE) {
        int2 d = *(const int2*)(dstp + e2 * 2);
        int2 s = *(const int2*)(srcp + e2 * 2);
        int p0 = atomicAdd(&g_cursor[d.x], 1);
        g_esrc[p0] = s.x;
        int p1 = atomicAdd(&g_cursor[d.y], 1);
        g_esrc[p1] = s.y;
    }
}

// ---------------- aggregation: zin = (1+eps)*h + segment_sum(h[src] by dst) ----------------
__global__ void k_agg(const float* __restrict__ hin, const float* __restrict__ epsp, int l) {
    int warp = (blockIdx.x * blockDim.x + threadIdx.x) >> 5;
    int lane = threadIdx.x & 31;
    if (warp >= NN) return;
    int beg = g_off[warp];
    int end = g_off[warp + 1];
    float4 acc = make_float4(0.f, 0.f, 0.f, 0.f);
    for (int j = beg; j < end; j += 32) {
        int myidx = j + lane;
        int s = (myidx < end) ? g_esrc[myidx] : 0;
        int cnt = min(32, end - j);
        int t = 0;
        for (; t + 4 <= cnt; t += 4) {
            int s0 = __shfl_sync(0xffffffffu, s, t);
            int s1 = __shfl_sync(0xffffffffu, s, t + 1);
            int s2 = __shfl_sync(0xffffffffu, s, t + 2);
            int s3 = __shfl_sync(0xffffffffu, s, t + 3);
            float4 v0 = *(const float4*)(hin + (size_t)s0 * DD + lane * 4);
            float4 v1 = *(const float4*)(hin + (size_t)s1 * DD + lane * 4);
            float4 v2 = *(const float4*)(hin + (size_t)s2 * DD + lane * 4);
            float4 v3 = *(const float4*)(hin + (size_t)s3 * DD + lane * 4);
            acc.x += v0.x + v1.x + v2.x + v3.x;
            acc.y += v0.y + v1.y + v2.y + v3.y;
            acc.z += v0.z + v1.z + v2.z + v3.z;
            acc.w += v0.w + v1.w + v2.w + v3.w;
        }
        for (; t < cnt; t++) {
            int sj = __shfl_sync(0xffffffffu, s, t);
            float4 v = *(const float4*)(hin + (size_t)sj * DD + lane * 4);
            acc.x += v.x; acc.y += v.y; acc.z += v.z; acc.w += v.w;
        }
    }
    float ev = 1.0f + epsp[l];
    float4 hv = *(const float4*)(hin + (size_t)warp * DD + lane * 4);
    acc.x += ev * hv.x; acc.y += ev * hv.y; acc.z += ev * hv.z; acc.w += ev * hv.w;
    *(float4*)(g_zin + (size_t)warp * DD + lane * 4) = acc;
}

// ---------------- split-bf16 tensor-core GEMM with fused epilogue ----------------
// C[M,Nn] = epilogue(A[M,K] @ B[K,Nn]) via  Ah*Bh + Ah*Bl + Al*Bh  (fp32 accum)
// B comes preconverted from Bimg (per-N-tile layout: [kt][hl][256 uint4])
#define BM 128
#define BN 128
#define BK 16
#define ASTR 24
#define BSTR 136

__device__ __forceinline__ void ldsm4(unsigned r[4], const __nv_bfloat16* p) {
    unsigned addr = (unsigned)__cvta_generic_to_shared(p);
    asm volatile("ldmatrix.sync.aligned.m8n8.x4.shared.b16 {%0,%1,%2,%3}, [%4];"
                 : "=r"(r[0]), "=r"(r[1]), "=r"(r[2]), "=r"(r[3]) : "r"(addr));
}
__device__ __forceinline__ void ldsm4t(unsigned r[4], const __nv_bfloat16* p) {
    unsigned addr = (unsigned)__cvta_generic_to_shared(p);
    asm volatile("ldmatrix.sync.aligned.m8n8.x4.trans.shared.b16 {%0,%1,%2,%3}, [%4];"
                 : "=r"(r[0]), "=r"(r[1]), "=r"(r[2]), "=r"(r[3]) : "r"(addr));
}
__device__ __forceinline__ void mma16816(float c[4], const unsigned a[4], unsigned b0, unsigned b1) {
    asm volatile("mma.sync.aligned.m16n8k16.row.col.f32.bf16.bf16.f32 "
                 "{%0,%1,%2,%3},{%4,%5,%6,%7},{%8,%9},{%0,%1,%2,%3};"
                 : "+f"(c[0]), "+f"(c[1]), "+f"(c[2]), "+f"(c[3])
                 : "r"(a[0]), "r"(a[1]), "r"(a[2]), "r"(a[3]), "r"(b0), "r"(b1));
}

__global__ __launch_bounds__(256, 2) void k_gemm(
    const float* __restrict__ A, const uint4* __restrict__ Bimg, float* __restrict__ C,
    int M, int Nn, int K,
    const float* __restrict__ scale, const float* __restrict__ shift, int fuse_relu) {
    __shared__ __align__(16) __nv_bfloat16 Ah[BM * ASTR];
    __shared__ __align__(16) __nv_bfloat16 Al[BM * ASTR];
    __shared__ __align__(16) __nv_bfloat16 Bh[BK * BSTR];
    __shared__ __align__(16) __nv_bfloat16 Bl[BK * BSTR];

    int tid = threadIdx.x;
    int lane = tid & 31, warp = tid >> 5;
    int wm = (warp >> 1) * 32;
    int wn = (warp & 1) * 64;
    int m0 = blockIdx.x * BM, n0 = blockIdx.y * BN;
    Bimg += (size_t)blockIdx.y * 4096;

    float acc[2][8][4];
#pragma unroll
    for (int i = 0; i < 2; i++)
#pragma unroll
        for (int j = 0; j < 8; j++)
#pragma unroll
            for (int q = 0; q < 4; q++) acc[i][j][q] = 0.f;

    float4 ar[2];
    uint4 brh, brl;
    const int a_row0 = tid >> 2, a_c4 = tid & 3;
    const int a_row1 = (tid + 256) >> 2;
    const int b_krow = tid >> 4, b_chunk = tid & 15;

#define LDG_TILE(kt)                                                                     \
    {                                                                                    \
        int gr0 = m0 + a_row0, gr1 = m0 + a_row1;                                        \
        int k0 = (kt) * BK;                                                              \
        ar[0] = (gr0 < M) ? *(const float4*)(A + (size_t)gr0 * K + k0 + a_c4 * 4)        \
                          : make_float4(0.f, 0.f, 0.f, 0.f);                             \
        ar[1] = (gr1 < M) ? *(const float4*)(A + (size_t)gr1 * K + k0 + a_c4 * 4)        \
                          : make_float4(0.f, 0.f, 0.f, 0.f);                             \
        brh = Bimg[(kt) * 512 + tid];                                                    \
        brl = Bimg[(kt) * 512 + 256 + tid];                                              \
    }

#define STS_TILE()                                                                       \
    {                                                                                    \
        _Pragma("unroll") for (int p = 0; p < 2; p++) {                                  \
            int arow = p ? a_row1 : a_row0;                                              \
            const float* v = (const float*)&ar[p];                                       \
            _Pragma("unroll") for (int j = 0; j < 2; j++) {                              \
                __nv_bfloat16 h0 = __float2bfloat16(v[2 * j]);                           \
                __nv_bfloat16 h1 = __float2bfloat16(v[2 * j + 1]);                       \
                __nv_bfloat16 l0 = __float2bfloat16(v[2 * j] - __bfloat162float(h0));    \
                __nv_bfloat16 l1 = __float2bfloat16(v[2 * j + 1] - __bfloat162float(h1));\
                *(__nv_bfloat162*)&Ah[arow * ASTR + a_c4 * 4 + 2 * j] =                  \
                    __nv_bfloat162(h0, h1);                                              \
                *(__nv_bfloat162*)&Al[arow * ASTR + a_c4 * 4 + 2 * j] =                  \
                    __nv_bfloat162(l0, l1);                                              \
            }                                                                            \
        }                                                                                \
        *(uint4*)&Bh[b_krow * BSTR + b_chunk * 8] = brh;                                 \
        *(uint4*)&Bl[b_krow * BSTR + b_chunk * 8] = brl;                                 \
    }

    const int a_lrow = wm + (lane & 15);
    const int a_lkof = (lane >> 4) * 8;
    const int b_lk = (lane & 7) + ((lane >> 3) & 1) * 8;
    const int b_lnof = ((lane >> 4) & 1) * 8;

    // load B fragments once (4 ldsm4t), reuse across passes
#define LDB(BS, bfr)                                                                     \
    {                                                                                    \
        _Pragma("unroll") for (int ntp = 0; ntp < 4; ntp++)                              \
            ldsm4t(bfr[ntp], &BS[b_lk * BSTR + wn + ntp * 16 + b_lnof]);                 \
    }
    // per-pass: load A fragments (2 ldsm4), MMA against given B fragments
#define PASSF(AS, bfr)                                                                   \
    {                                                                                    \
        unsigned afr[2][4];                                                              \
        _Pragma("unroll") for (int mt = 0; mt < 2; mt++)                                 \
            ldsm4(afr[mt], &AS[(a_lrow + mt * 16) * ASTR + a_lkof]);                     \
        _Pragma("unroll") for (int mt = 0; mt < 2; mt++)                                 \
            _Pragma("unroll") for (int ntp = 0; ntp < 4; ntp++) {                        \
                mma16816(acc[mt][2 * ntp], afr[mt], bfr[ntp][0], bfr[ntp][1]);           \
                mma16816(acc[mt][2 * ntp + 1], afr[mt], bfr[ntp][2], bfr[ntp][3]);       \
            }                                                                            \
    }

    LDG_TILE(0);
    STS_TILE();
    __syncthreads();
    int nIter = K / BK;
    for (int t = 0; t < nIter; t++) {
        bool have = (t + 1 < nIter);
        if (have) LDG_TILE(t + 1);
        {
            unsigned bfr[4][4];
            LDB(Bh, bfr);          // Bh fragments
            PASSF(Ah, bfr);        // Ah*Bh
            PASSF(Al, bfr);        // Al*Bh (reuse Bh frags)
            LDB(Bl, bfr);          // Bl fragments
            PASSF(Ah, bfr);        // Ah*Bl
        }
        __syncthreads();
        if (have) {
            STS_TILE();
            __syncthreads();
        }
    }

    int grp = lane >> 2, tig = lane & 3;
#pragma unroll
    for (int mt = 0; mt < 2; mt++) {
#pragma unroll
        for (int nt = 0; nt < 8; nt++) {
            int col = n0 + wn + nt * 8 + tig * 2;
            float2 sc = make_float2(0.f, 0.f), sh;
            sh = *(const float2*)(shift + col);
            if (fuse_relu) sc = *(const float2*)(scale + col);
            int row0 = m0 + wm + mt * 16 + grp;
            int row1 = row0 + 8;
            float* c = acc[mt][nt];
            float2 o0, o1;
            if (fuse_relu) {
                o0.x = fmaxf(c[0] * sc.x + sh.x, 0.f);
                o0.y = fmaxf(c[1] * sc.y + sh.y, 0.f);
                o1.x = fmaxf(c[2] * sc.x + sh.x, 0.f);
                o1.y = fmaxf(c[3] * sc.y + sh.y, 0.f);
            } else {
                o0.x = c[0] + sh.x;
                o0.y = c[1] + sh.y;
                o1.x = c[2] + sh.x;
                o1.y = c[3] + sh.y;
            }
            if (row0 < M) *(float2*)(C + (size_t)row0 * Nn + col) = o0;
            if (row1 < M) *(float2*)(C + (size_t)row1 * Nn + col) = o1;
        }
    }
#undef LDG_TILE
#undef STS_TILE
#undef LDB
#undef PASSF
}

// ---------------- log_softmax over D=128, warp per row, in place (fast-math) ----------------
__global__ void k_lsm(float* __restrict__ out) {
    int warp = (blockIdx.x * blockDim.x + threadIdx.x) >> 5;
    int lane = threadIdx.x & 31;
    if (warp >= NN) return;
    float4 v = *(float4*)(out + (size_t)warp * DD + lane * 4);
    float mx = fmaxf(fmaxf(v.x, v.y), fmaxf(v.z, v.w));
#pragma unroll
    for (int o = 16; o; o >>= 1) mx = fmaxf(mx, __shfl_xor_sync(0xffffffffu, mx, o));
    float s = __expf(v.x - mx) + __expf(v.y - mx) + __expf(v.z - mx) + __expf(v.w - mx);
#pragma unroll
    for (int o = 16; o; o >>= 1) s += __shfl_xor_sync(0xffffffffu, s, o);
    float lse = mx + __logf(s);
    v.x -= lse; v.y -= lse; v.z -= lse; v.w -= lse;
    *(float4*)(out + (size_t)warp * DD + lane * 4) = v;
}

// ---------------- launch ----------------
extern "C" void kernel_launch(void* const* d_in, const int* in_sizes, int n_in,
                              void* d_out, int out_size) {
    const float* x   = (const float*)d_in[0];
    const int*   ei  = (const int*)d_in[1];
    const float* W1  = (const float*)d_in[2];
    const float* b1  = (const float*)d_in[3];
    const float* g1  = (const float*)d_in[4];
    const float* be1 = (const float*)d_in[5];
    const float* m1  = (const float*)d_in[6];
    const float* v1  = (const float*)d_in[7];
    const float* W2  = (const float*)d_in[8];
    const float* b2  = (const float*)d_in[9];
    const float* eps = (const float*)d_in[10];
    const float* go  = (const float*)d_in[11];
    const float* bo  = (const float*)d_in[12];
    const float* mo  = (const float*)d_in[13];
    const float* vo  = (const float*)d_in[14];
    const int* srcp = ei;
    const int* dstp = ei + EE;

    float *zin, *z1p, *hA, *hB, *sc1, *sh1, *sc2, *sh2;
    uint4 *w1i, *w2i;
    cudaGetSymbolAddress((void**)&zin, g_zin);
    cudaGetSymbolAddress((void**)&z1p, g_z1);
    cudaGetSymbolAddress((void**)&hA, g_hA);
    cudaGetSymbolAddress((void**)&hB, g_hB);
    cudaGetSymbolAddress((void**)&sc1, g_sc1);
    cudaGetSymbolAddress((void**)&sh1, g_sh1);
    cudaGetSymbolAddress((void**)&sc2, g_sc2);
    cudaGetSymbolAddress((void**)&sh2, g_sh2);
    cudaGetSymbolAddress((void**)&w1i, g_w1img);
    cudaGetSymbolAddress((void**)&w2i, g_w2img);

    k_prep<<<3, 256>>>(b1, g1, be1, m1, v1, b2, go, bo, mo, vo);
    k_wimg<<<192, 256>>>(W1, W2);
    k_zero_cnt<<<(NN + 255) / 256, 256>>>();
    k_hist<<<(EE / 2 + 255) / 256, 256>>>(dstp);
    const int SB = (NN + 255) / 256;  // 196
    k_bsum<<<SB, 256>>>();
    k_bscan<<<1, 256>>>();
    k_apply<<<SB, 256>>>();
    k_fill<<<(EE / 2 + 255) / 256, 256>>>(srcp, dstp);

    const int MT = (NN + BM - 1) / BM;  // 391
    for (int l = 0; l < LL; l++) {
        const float* hin = (l == 0) ? x : ((l == 1) ? hA : hB);
        k_agg<<<(NN * 32 + 255) / 256, 256>>>(hin, eps, l);
        k_gemm<<<dim3(MT, 2), 256>>>(zin, w1i + (size_t)l * 2 * 4096, z1p,
                                     NN, 2 * DD, DD, sc1 + l * 256, sh1 + l * 256, 1);
        if (l < 2) {
            float* hout = (l == 0) ? hA : hB;
            k_gemm<<<dim3(MT, 1), 256>>>(z1p, w2i + (size_t)l * 8192, hout,
                                         NN, DD, 2 * DD, sc2 + l * 128, sh2 + l * 128, 1);
        } else {
            k_gemm<<<dim3(MT, 1), 256>>>(z1p, w2i + (size_t)2 * 8192, (float*)d_out,
                                         NN, DD, 2 * DD, nullptr, b2 + 2 * 128, 0);
        }
    }
    k_lsm<<<(NN * 32 + 255) / 256, 256>>>((float*)d_out);
}